// round 10
// baseline (speedup 1.0000x reference)
#include <cuda_runtime.h>
#include <cuda_fp16.h>
#include <cuda_bf16.h>
#include <cstdint>

// ---------------------------------------------------------------------------
// MultiResImplicitFeature R10: R9 with the alignment bug fixed.
//  - RSTRIDE = 56 -> warp's smem slice is EXACTLY its contiguous output
//    block (32 rows x 56 floats); all smem float4 accesses 16B-aligned.
//  - flush: lane reads 8 linear floats (2x LDS.128), writes st.global.cs.v8.
//  - grids: pair-duplicated fp16 channel-last entries (32 B), trilerp =
//    4 x ld.global.v8.f32 per grid.
//  - no block barriers; __launch_bounds__(192,5) -> 30 warps/SM.
// ---------------------------------------------------------------------------

static constexpr int RES0 = 16, RES1 = 32, RES2 = 64, RES3 = 128;
static constexpr int S0 = RES0*RES0*RES0;
static constexpr int S1 = RES1*RES1*RES1;
static constexpr int S2 = RES2*RES2*RES2;
static constexpr int S3 = RES3*RES3*RES3;
static constexpr long long OFF0 = 0;
static constexpr long long OFF1 = (long long)S0*8;
static constexpr long long OFF2 = OFF1 + (long long)S1*8;
static constexpr long long OFF3 = OFF2 + (long long)S2*8;
static constexpr long long GTOTAL = OFF3 + (long long)S3*8;   // 76.7 MB

__device__ __align__(256) uint32_t g_grids[GTOTAL];

__device__ __forceinline__ void ldg256(const uint32_t* p, uint32_t r[8]) {
    asm volatile("ld.global.v8.f32 {%0,%1,%2,%3,%4,%5,%6,%7}, [%8];"
                 : "=r"(r[0]), "=r"(r[1]), "=r"(r[2]), "=r"(r[3]),
                   "=r"(r[4]), "=r"(r[5]), "=r"(r[6]), "=r"(r[7])
                 : "l"(p));
}

__device__ __forceinline__ void stg256cs(float* p, const float* v) {
    asm volatile("st.global.cs.v8.f32 [%0], {%1,%2,%3,%4,%5,%6,%7,%8};"
                 :: "l"(p), "f"(v[0]), "f"(v[1]), "f"(v[2]), "f"(v[3]),
                    "f"(v[4]), "f"(v[5]), "f"(v[6]), "f"(v[7])
                 : "memory");
}

// ---------------- fused transpose (one launch, all grids) -----------------

template <int R>
__device__ __forceinline__ void do_transpose(const float* __restrict__ in,
                                             uint32_t* __restrict__ out, int i) {
    constexpr int S = R * R * R;
    int x = i & (R - 1);
    int i2 = (x < R - 1) ? i + 1 : i;
    __half h[16];
#pragma unroll
    for (int c = 0; c < 8; c++) {
        h[c]     = __float2half(__ldcs(in + (long long)c * S + i));
        h[8 + c] = __float2half(__ldcs(in + (long long)c * S + i2));
    }
    uint4* dst = reinterpret_cast<uint4*>(out + (long long)i * 8);
    const uint4* src = reinterpret_cast<const uint4*>(h);
    dst[0] = src[0];
    dst[1] = src[1];
}

static constexpr int TTOT = S3 + S2 + S1 + S0;

__global__ void __launch_bounds__(256)
fused_transpose_kernel(const float* __restrict__ g0, const float* __restrict__ g1,
                       const float* __restrict__ g2, const float* __restrict__ g3) {
    int u = blockIdx.x * blockDim.x + threadIdx.x;
    if (u < S3) {
        do_transpose<RES3>(g3, g_grids + OFF3, u);
    } else if (u < S3 + S2) {
        do_transpose<RES2>(g2, g_grids + OFF2, u - S3);
    } else if (u < S3 + S2 + S1) {
        do_transpose<RES1>(g1, g_grids + OFF1, u - S3 - S2);
    } else if (u < TTOT) {
        do_transpose<RES0>(g0, g_grids + OFF0, u - S3 - S2 - S1);
    }
}

// ---------------- main kernel ---------------------------------------------

struct TLerp {
    const uint32_t* a[4];
    float wzy[4];
    float wx;
};

template <int R>
__device__ __forceinline__ TLerp prep(const uint32_t* __restrict__ g,
                                      float px, float py, float pz) {
    const float scale = 0.5f * (float)(R - 1);
    float cx = (px + 1.0f) * scale;
    float cy = (py + 1.0f) * scale;
    float cz = (pz + 1.0f) * scale;
    float fx = floorf(cx), fy = floorf(cy), fz = floorf(cz);
    int x0 = (int)fx; x0 = max(0, min(x0, R - 1));
    int y0 = (int)fy; y0 = max(0, min(y0, R - 1));
    int z0 = (int)fz; z0 = max(0, min(z0, R - 1));
    int y1 = min(y0 + 1, R - 1);
    int z1 = min(z0 + 1, R - 1);
    float wx = cx - fx, wy = cy - fy, wz = cz - fz;

    TLerp t;
    t.wx = wx;
    long long b00 = ((long long)z0 * R + y0) * R + x0;
    long long b01 = ((long long)z0 * R + y1) * R + x0;
    long long b10 = ((long long)z1 * R + y0) * R + x0;
    long long b11 = ((long long)z1 * R + y1) * R + x0;
    t.a[0] = g + (b00 << 3);
    t.a[1] = g + (b01 << 3);
    t.a[2] = g + (b10 << 3);
    t.a[3] = g + (b11 << 3);
    t.wzy[0] = (1.0f - wz) * (1.0f - wy);
    t.wzy[1] = (1.0f - wz) * wy;
    t.wzy[2] = wz * (1.0f - wy);
    t.wzy[3] = wz * wy;
    return t;
}

__device__ __forceinline__ void load4(const TLerp& t, uint32_t r[4][8]) {
#pragma unroll
    for (int c = 0; c < 4; c++) ldg256(t.a[c], r[c]);
}

__device__ __forceinline__ void accum4(const TLerp& t, const uint32_t r[4][8],
                                       float* __restrict__ acc) {
    float wxl = 1.0f - t.wx;
    float wxr = t.wx;
#pragma unroll
    for (int c = 0; c < 4; c++) {
        float wl = t.wzy[c] * wxl;
        float wr = t.wzy[c] * wxr;
#pragma unroll
        for (int k = 0; k < 4; k++) {
            float2 a = __half22float2(*reinterpret_cast<const __half2*>(&r[c][k]));
            float2 b = __half22float2(*reinterpret_cast<const __half2*>(&r[c][4 + k]));
            acc[2*k]   = fmaf(wl, a.x, fmaf(wr, b.x, acc[2*k]));
            acc[2*k+1] = fmaf(wl, a.y, fmaf(wr, b.y, acc[2*k+1]));
        }
    }
}

static constexpr int WARPS_PB = 6;      // 192 threads
static constexpr int RSTRIDE = 56;      // contiguous rows; 224B base -> 16B aligned

__global__ void __launch_bounds__(192, 5)
mrif_main_kernel(const float* __restrict__ x, float* __restrict__ out, int n) {
    __shared__ float smem[WARPS_PB * 32 * RSTRIDE];   // 43,008 B

    int wid = threadIdx.x >> 5;
    int lane = threadIdx.x & 31;
    long long warpBase = ((long long)blockIdx.x * WARPS_PB + wid) << 5;
    long long i = warpBase + lane;
    float* ws = smem + wid * 32 * RSTRIDE;
    float* row = ws + lane * RSTRIDE;

    if (i < n) {
        float px = __ldg(x + 3 * i + 0);
        float py = __ldg(x + 3 * i + 1);
        float pz = __ldg(x + 3 * i + 2);

        // All gather addresses first.
        TLerp t0 = prep<RES0>(g_grids + OFF0, px, py, pz);
        TLerp t1 = prep<RES1>(g_grids + OFF1, px, py, pz);
        TLerp t2 = prep<RES2>(g_grids + OFF2, px, py, pz);
        TLerp t3 = prep<RES3>(g_grids + OFF3, px, py, pz);

        // First load wave.
        uint32_t r0[4][8], r1[4][8];
        load4(t0, r0);
        load4(t1, r1);

        // sincos overlapped with loads in flight; results straight to smem.
        {
            const float HPI = 1.57079632679489662f;
            float p[3] = {px, py, pz};
            float sc[24];
#pragma unroll
            for (int l = 0; l < 4; l++) {
#pragma unroll
                for (int d = 0; d < 3; d++) {
                    float sv, cv;
                    __sincosf(HPI * (float)(l + 1) * p[d], &sv, &cv);
                    sc[l * 3 + d] = sv;
                    sc[12 + l * 3 + d] = cv;
                }
            }
#pragma unroll
            for (int k = 0; k < 6; k++)
                *reinterpret_cast<float4*>(row + 4 * k) =
                    make_float4(sc[4*k], sc[4*k+1], sc[4*k+2], sc[4*k+3]);
        }

        // Second wave + consumption; each grid's 8 feats to smem.
        uint32_t r2[4][8];
        load4(t2, r2);
        float f[8];
#pragma unroll
        for (int c = 0; c < 8; c++) f[c] = 0.0f;
        accum4(t0, r0, f);
        *reinterpret_cast<float4*>(row + 24) = make_float4(f[0], f[1], f[2], f[3]);
        *reinterpret_cast<float4*>(row + 28) = make_float4(f[4], f[5], f[6], f[7]);

        uint32_t r3[4][8];
        load4(t3, r3);
#pragma unroll
        for (int c = 0; c < 8; c++) f[c] = 0.0f;
        accum4(t1, r1, f);
        *reinterpret_cast<float4*>(row + 32) = make_float4(f[0], f[1], f[2], f[3]);
        *reinterpret_cast<float4*>(row + 36) = make_float4(f[4], f[5], f[6], f[7]);

#pragma unroll
        for (int c = 0; c < 8; c++) f[c] = 0.0f;
        accum4(t2, r2, f);
        *reinterpret_cast<float4*>(row + 40) = make_float4(f[0], f[1], f[2], f[3]);
        *reinterpret_cast<float4*>(row + 44) = make_float4(f[4], f[5], f[6], f[7]);

#pragma unroll
        for (int c = 0; c < 8; c++) f[c] = 0.0f;
        accum4(t3, r3, f);
        *reinterpret_cast<float4*>(row + 48) = make_float4(f[0], f[1], f[2], f[3]);
        *reinterpret_cast<float4*>(row + 52) = make_float4(f[4], f[5], f[6], f[7]);
    }
    __syncwarp();

    // Warp flush: valid*56 contiguous floats (layout in smem is already
    // exactly the output layout) via coalesced 256-bit stores.
    long long rem = n - warpBase;
    int valid = (rem >= 32) ? 32 : (rem > 0 ? (int)rem : 0);
    int total = valid * 56;
    float* obase = out + warpBase * 56;
#pragma unroll
    for (int it = 0; it < 7; it++) {
        int w = it * 256 + lane * 8;
        if (w < total) {
            float4 a = *reinterpret_cast<const float4*>(ws + w);
            float4 b = *reinterpret_cast<const float4*>(ws + w + 4);
            float v[8] = {a.x, a.y, a.z, a.w, b.x, b.y, b.z, b.w};
            stg256cs(obase + w, v);
        }
    }
}

extern "C" void kernel_launch(void* const* d_in, const int* in_sizes, int n_in,
                              void* d_out, int out_size) {
    const float* x  = (const float*)d_in[0];
    const float* g0 = (const float*)d_in[1];
    const float* g1 = (const float*)d_in[2];
    const float* g2 = (const float*)d_in[3];
    const float* g3 = (const float*)d_in[4];
    float* out = (float*)d_out;

    int n = in_sizes[0] / 3;

    const int TT = 256;
    fused_transpose_kernel<<<(TTOT + TT - 1) / TT, TT>>>(g0, g1, g2, g3);

    int npw = 192;   // points per block
    mrif_main_kernel<<<(n + npw - 1) / npw, 192>>>(x, out, n);
}

// round 11
// speedup vs baseline: 1.9591x; 1.9591x over previous
#include <cuda_runtime.h>
#include <cuda_fp16.h>
#include <cuda_bf16.h>
#include <cstdint>

// ---------------------------------------------------------------------------
// MultiResImplicitFeature R11: R8 algorithm with progressive v8 stores
// (no row[56] buffer) + __launch_bounds__(256,4) for 32 warps/SM.
//  - grids: pair-duplicated fp16 channel-last entries (32 B):
//      entry(z,y,x) = [8ch of voxel x | 8ch of voxel min(x+1,R-1)]
//    trilerp = 4 x ld.global.v8.f32
//  - output: 7 x st.global.cs.v8.f32 per row, emitted as results are ready.
// ---------------------------------------------------------------------------

static constexpr int RES0 = 16, RES1 = 32, RES2 = 64, RES3 = 128;
static constexpr int S0 = RES0*RES0*RES0;
static constexpr int S1 = RES1*RES1*RES1;
static constexpr int S2 = RES2*RES2*RES2;
static constexpr int S3 = RES3*RES3*RES3;
static constexpr long long OFF0 = 0;
static constexpr long long OFF1 = (long long)S0*8;
static constexpr long long OFF2 = OFF1 + (long long)S1*8;
static constexpr long long OFF3 = OFF2 + (long long)S2*8;
static constexpr long long GTOTAL = OFF3 + (long long)S3*8;   // 76.7 MB

__device__ __align__(256) uint32_t g_grids[GTOTAL];

__device__ __forceinline__ void ldg256(const uint32_t* p, uint32_t r[8]) {
    asm volatile("ld.global.v8.f32 {%0,%1,%2,%3,%4,%5,%6,%7}, [%8];"
                 : "=r"(r[0]), "=r"(r[1]), "=r"(r[2]), "=r"(r[3]),
                   "=r"(r[4]), "=r"(r[5]), "=r"(r[6]), "=r"(r[7])
                 : "l"(p));
}

__device__ __forceinline__ void stg256cs(float* p, const float* v) {
    asm volatile("st.global.cs.v8.f32 [%0], {%1,%2,%3,%4,%5,%6,%7,%8};"
                 :: "l"(p), "f"(v[0]), "f"(v[1]), "f"(v[2]), "f"(v[3]),
                    "f"(v[4]), "f"(v[5]), "f"(v[6]), "f"(v[7])
                 : "memory");
}

// ---------------- fused transpose (one launch, all grids) -----------------

template <int R>
__device__ __forceinline__ void do_transpose(const float* __restrict__ in,
                                             uint32_t* __restrict__ out, int i) {
    constexpr int S = R * R * R;
    int x = i & (R - 1);
    int i2 = (x < R - 1) ? i + 1 : i;
    __half h[16];
#pragma unroll
    for (int c = 0; c < 8; c++) {
        h[c]     = __float2half(__ldcs(in + (long long)c * S + i));
        h[8 + c] = __float2half(__ldcs(in + (long long)c * S + i2));
    }
    uint4* dst = reinterpret_cast<uint4*>(out + (long long)i * 8);
    const uint4* src = reinterpret_cast<const uint4*>(h);
    dst[0] = src[0];
    dst[1] = src[1];
}

static constexpr int TTOT = S3 + S2 + S1 + S0;

__global__ void __launch_bounds__(256)
fused_transpose_kernel(const float* __restrict__ g0, const float* __restrict__ g1,
                       const float* __restrict__ g2, const float* __restrict__ g3) {
    int u = blockIdx.x * blockDim.x + threadIdx.x;
    if (u < S3) {
        do_transpose<RES3>(g3, g_grids + OFF3, u);
    } else if (u < S3 + S2) {
        do_transpose<RES2>(g2, g_grids + OFF2, u - S3);
    } else if (u < S3 + S2 + S1) {
        do_transpose<RES1>(g1, g_grids + OFF1, u - S3 - S2);
    } else if (u < TTOT) {
        do_transpose<RES0>(g0, g_grids + OFF0, u - S3 - S2 - S1);
    }
}

// ---------------- main kernel ---------------------------------------------

struct TLerp {
    const uint32_t* a[4];
    float wzy[4];
    float wx;
};

template <int R>
__device__ __forceinline__ TLerp prep(const uint32_t* __restrict__ g,
                                      float px, float py, float pz) {
    const float scale = 0.5f * (float)(R - 1);
    float cx = (px + 1.0f) * scale;
    float cy = (py + 1.0f) * scale;
    float cz = (pz + 1.0f) * scale;
    float fx = floorf(cx), fy = floorf(cy), fz = floorf(cz);
    int x0 = (int)fx; x0 = max(0, min(x0, R - 1));
    int y0 = (int)fy; y0 = max(0, min(y0, R - 1));
    int z0 = (int)fz; z0 = max(0, min(z0, R - 1));
    int y1 = min(y0 + 1, R - 1);
    int z1 = min(z0 + 1, R - 1);
    float wx = cx - fx, wy = cy - fy, wz = cz - fz;

    TLerp t;
    t.wx = wx;
    long long b00 = ((long long)z0 * R + y0) * R + x0;
    long long b01 = ((long long)z0 * R + y1) * R + x0;
    long long b10 = ((long long)z1 * R + y0) * R + x0;
    long long b11 = ((long long)z1 * R + y1) * R + x0;
    t.a[0] = g + (b00 << 3);
    t.a[1] = g + (b01 << 3);
    t.a[2] = g + (b10 << 3);
    t.a[3] = g + (b11 << 3);
    t.wzy[0] = (1.0f - wz) * (1.0f - wy);
    t.wzy[1] = (1.0f - wz) * wy;
    t.wzy[2] = wz * (1.0f - wy);
    t.wzy[3] = wz * wy;
    return t;
}

__device__ __forceinline__ void load4(const TLerp& t, uint32_t r[4][8]) {
#pragma unroll
    for (int c = 0; c < 4; c++) ldg256(t.a[c], r[c]);
}

__device__ __forceinline__ void accum4(const TLerp& t, const uint32_t r[4][8],
                                       float* __restrict__ acc) {
    float wxl = 1.0f - t.wx;
    float wxr = t.wx;
#pragma unroll
    for (int c = 0; c < 4; c++) {
        float wl = t.wzy[c] * wxl;
        float wr = t.wzy[c] * wxr;
#pragma unroll
        for (int k = 0; k < 4; k++) {
            float2 a = __half22float2(*reinterpret_cast<const __half2*>(&r[c][k]));
            float2 b = __half22float2(*reinterpret_cast<const __half2*>(&r[c][4 + k]));
            acc[2*k]   = fmaf(wl, a.x, fmaf(wr, b.x, acc[2*k]));
            acc[2*k+1] = fmaf(wl, a.y, fmaf(wr, b.y, acc[2*k+1]));
        }
    }
}

__global__ void __launch_bounds__(256, 4)
mrif_main_kernel(const float* __restrict__ x, float* __restrict__ out, int n) {
    int i = blockIdx.x * blockDim.x + threadIdx.x;
    if (i >= n) return;

    float px = __ldg(x + 3LL * i + 0);
    float py = __ldg(x + 3LL * i + 1);
    float pz = __ldg(x + 3LL * i + 2);

    float* orow = out + (long long)i * 56;

    // Addresses for all four grids (pure ALU).
    TLerp t0 = prep<RES0>(g_grids + OFF0, px, py, pz);
    TLerp t1 = prep<RES1>(g_grids + OFF1, px, py, pz);
    TLerp t2 = prep<RES2>(g_grids + OFF2, px, py, pz);
    TLerp t3 = prep<RES3>(g_grids + OFF3, px, py, pz);

    // First load wave (grids 0,1) in flight during sincos.
    uint32_t r0[4][8], r1[4][8];
    load4(t0, r0);
    load4(t1, r1);

    // Fourier features, stored immediately (3 x v8).
    {
        const float HPI = 1.57079632679489662f;
        float p[3] = {px, py, pz};
        float sc[24];
#pragma unroll
        for (int l = 0; l < 4; l++) {
#pragma unroll
            for (int d = 0; d < 3; d++) {
                float sv, cv;
                __sincosf(HPI * (float)(l + 1) * p[d], &sv, &cv);
                sc[l * 3 + d] = sv;
                sc[12 + l * 3 + d] = cv;
            }
        }
        stg256cs(orow + 0,  sc + 0);
        stg256cs(orow + 8,  sc + 8);
        stg256cs(orow + 16, sc + 16);
    }

    // Second wave + consumption, each grid stored as soon as it's reduced.
    float f[8];
    uint32_t r2[4][8];
    load4(t2, r2);
#pragma unroll
    for (int c = 0; c < 8; c++) f[c] = 0.0f;
    accum4(t0, r0, f);
    stg256cs(orow + 24, f);

    uint32_t r3[4][8];
    load4(t3, r3);
#pragma unroll
    for (int c = 0; c < 8; c++) f[c] = 0.0f;
    accum4(t1, r1, f);
    stg256cs(orow + 32, f);

#pragma unroll
    for (int c = 0; c < 8; c++) f[c] = 0.0f;
    accum4(t2, r2, f);
    stg256cs(orow + 40, f);

#pragma unroll
    for (int c = 0; c < 8; c++) f[c] = 0.0f;
    accum4(t3, r3, f);
    stg256cs(orow + 48, f);
}

extern "C" void kernel_launch(void* const* d_in, const int* in_sizes, int n_in,
                              void* d_out, int out_size) {
    const float* x  = (const float*)d_in[0];
    const float* g0 = (const float*)d_in[1];
    const float* g1 = (const float*)d_in[2];
    const float* g2 = (const float*)d_in[3];
    const float* g3 = (const float*)d_in[4];
    float* out = (float*)d_out;

    int n = in_sizes[0] / 3;

    const int TT = 256;
    fused_transpose_kernel<<<(TTOT + TT - 1) / TT, TT>>>(g0, g1, g2, g3);
    mrif_main_kernel<<<(n + 255) / 256, 256>>>(x, out, n);
}

// round 12
// speedup vs baseline: 2.1746x; 1.1100x over previous
#include <cuda_runtime.h>
#include <cuda_fp16.h>
#include <cuda_bf16.h>
#include <cstdint>

// ---------------------------------------------------------------------------
// MultiResImplicitFeature R12: R8 (champion) + harmonic-recurrence Fourier
// features: 3 __sincosf per point instead of 12 (MUFU pressure / 4), with
// k=2,3,4 harmonics generated by FMA identities.
//  - grids: pair-duplicated fp16 channel-last entries (32 B):
//      entry(z,y,x) = [8ch of voxel x | 8ch of voxel min(x+1,R-1)]
//    trilerp = 4 x ld.global.v8.f32
//  - output row buffered in registers, 7 consecutive st.global.cs.v8.f32
//    (keeps L2 write-merging; R11 showed spreading them costs DRAM BW).
// ---------------------------------------------------------------------------

static constexpr int RES0 = 16, RES1 = 32, RES2 = 64, RES3 = 128;
static constexpr int S0 = RES0*RES0*RES0;
static constexpr int S1 = RES1*RES1*RES1;
static constexpr int S2 = RES2*RES2*RES2;
static constexpr int S3 = RES3*RES3*RES3;
static constexpr long long OFF0 = 0;
static constexpr long long OFF1 = (long long)S0*8;
static constexpr long long OFF2 = OFF1 + (long long)S1*8;
static constexpr long long OFF3 = OFF2 + (long long)S2*8;
static constexpr long long GTOTAL = OFF3 + (long long)S3*8;   // 76.7 MB

__device__ __align__(256) uint32_t g_grids[GTOTAL];

__device__ __forceinline__ void ldg256(const uint32_t* p, uint32_t r[8]) {
    asm volatile("ld.global.v8.f32 {%0,%1,%2,%3,%4,%5,%6,%7}, [%8];"
                 : "=r"(r[0]), "=r"(r[1]), "=r"(r[2]), "=r"(r[3]),
                   "=r"(r[4]), "=r"(r[5]), "=r"(r[6]), "=r"(r[7])
                 : "l"(p));
}

__device__ __forceinline__ void stg256cs(float* p, const float* v) {
    asm volatile("st.global.cs.v8.f32 [%0], {%1,%2,%3,%4,%5,%6,%7,%8};"
                 :: "l"(p), "f"(v[0]), "f"(v[1]), "f"(v[2]), "f"(v[3]),
                    "f"(v[4]), "f"(v[5]), "f"(v[6]), "f"(v[7])
                 : "memory");
}

// ---------------- fused transpose (one launch, all grids) -----------------

template <int R>
__device__ __forceinline__ void do_transpose(const float* __restrict__ in,
                                             uint32_t* __restrict__ out, int i) {
    constexpr int S = R * R * R;
    int x = i & (R - 1);
    int i2 = (x < R - 1) ? i + 1 : i;
    __half h[16];
#pragma unroll
    for (int c = 0; c < 8; c++) {
        h[c]     = __float2half(__ldcs(in + (long long)c * S + i));
        h[8 + c] = __float2half(__ldcs(in + (long long)c * S + i2));
    }
    uint4* dst = reinterpret_cast<uint4*>(out + (long long)i * 8);
    const uint4* src = reinterpret_cast<const uint4*>(h);
    dst[0] = src[0];
    dst[1] = src[1];
}

static constexpr int TTOT = S3 + S2 + S1 + S0;

__global__ void __launch_bounds__(256)
fused_transpose_kernel(const float* __restrict__ g0, const float* __restrict__ g1,
                       const float* __restrict__ g2, const float* __restrict__ g3) {
    int u = blockIdx.x * blockDim.x + threadIdx.x;
    if (u < S3) {
        do_transpose<RES3>(g3, g_grids + OFF3, u);
    } else if (u < S3 + S2) {
        do_transpose<RES2>(g2, g_grids + OFF2, u - S3);
    } else if (u < S3 + S2 + S1) {
        do_transpose<RES1>(g1, g_grids + OFF1, u - S3 - S2);
    } else if (u < TTOT) {
        do_transpose<RES0>(g0, g_grids + OFF0, u - S3 - S2 - S1);
    }
}

// ---------------- main kernel ---------------------------------------------

struct TLerp {
    const uint32_t* a[4];
    float wzy[4];
    float wx;
};

template <int R>
__device__ __forceinline__ TLerp prep(const uint32_t* __restrict__ g,
                                      float px, float py, float pz) {
    const float scale = 0.5f * (float)(R - 1);
    float cx = (px + 1.0f) * scale;
    float cy = (py + 1.0f) * scale;
    float cz = (pz + 1.0f) * scale;
    float fx = floorf(cx), fy = floorf(cy), fz = floorf(cz);
    int x0 = (int)fx; x0 = max(0, min(x0, R - 1));
    int y0 = (int)fy; y0 = max(0, min(y0, R - 1));
    int z0 = (int)fz; z0 = max(0, min(z0, R - 1));
    int y1 = min(y0 + 1, R - 1);
    int z1 = min(z0 + 1, R - 1);
    float wx = cx - fx, wy = cy - fy, wz = cz - fz;

    TLerp t;
    t.wx = wx;
    long long b00 = ((long long)z0 * R + y0) * R + x0;
    long long b01 = ((long long)z0 * R + y1) * R + x0;
    long long b10 = ((long long)z1 * R + y0) * R + x0;
    long long b11 = ((long long)z1 * R + y1) * R + x0;
    t.a[0] = g + (b00 << 3);
    t.a[1] = g + (b01 << 3);
    t.a[2] = g + (b10 << 3);
    t.a[3] = g + (b11 << 3);
    t.wzy[0] = (1.0f - wz) * (1.0f - wy);
    t.wzy[1] = (1.0f - wz) * wy;
    t.wzy[2] = wz * (1.0f - wy);
    t.wzy[3] = wz * wy;
    return t;
}

__device__ __forceinline__ void load4(const TLerp& t, uint32_t r[4][8]) {
#pragma unroll
    for (int c = 0; c < 4; c++) ldg256(t.a[c], r[c]);
}

__device__ __forceinline__ void accum4(const TLerp& t, const uint32_t r[4][8],
                                       float* __restrict__ acc) {
    float wxl = 1.0f - t.wx;
    float wxr = t.wx;
#pragma unroll
    for (int c = 0; c < 4; c++) {
        float wl = t.wzy[c] * wxl;
        float wr = t.wzy[c] * wxr;
#pragma unroll
        for (int k = 0; k < 4; k++) {
            float2 a = __half22float2(*reinterpret_cast<const __half2*>(&r[c][k]));
            float2 b = __half22float2(*reinterpret_cast<const __half2*>(&r[c][4 + k]));
            acc[2*k]   = fmaf(wl, a.x, fmaf(wr, b.x, acc[2*k]));
            acc[2*k+1] = fmaf(wl, a.y, fmaf(wr, b.y, acc[2*k+1]));
        }
    }
}

__global__ void __launch_bounds__(256)
mrif_main_kernel(const float* __restrict__ x, float* __restrict__ out, int n) {
    int i = blockIdx.x * blockDim.x + threadIdx.x;
    if (i >= n) return;

    float px = __ldg(x + 3LL * i + 0);
    float py = __ldg(x + 3LL * i + 1);
    float pz = __ldg(x + 3LL * i + 2);

    // Phase 1: all gather addresses (pure ALU).
    TLerp t0 = prep<RES0>(g_grids + OFF0, px, py, pz);
    TLerp t1 = prep<RES1>(g_grids + OFF1, px, py, pz);
    TLerp t2 = prep<RES2>(g_grids + OFF2, px, py, pz);
    TLerp t3 = prep<RES3>(g_grids + OFF3, px, py, pz);

    // Phase 2: first load wave (grids 0,1).
    uint32_t r0[4][8], r1[4][8];
    load4(t0, r0);
    load4(t1, r1);

    // Phase 3: Fourier features via 3 sincos + harmonic recurrences.
    float row[56];
    {
        const float HPI = 1.57079632679489662f;
        float p[3] = {px, py, pz};
#pragma unroll
        for (int d = 0; d < 3; d++) {
            float s1, c1;
            __sincosf(HPI * p[d], &s1, &c1);
            float s2 = 2.0f * s1 * c1;
            float c2 = fmaf(-2.0f * s1, s1, 1.0f);
            float s3 = fmaf(s2, c1, c2 * s1);
            float c3 = fmaf(c2, c1, -s2 * s1);
            float s4 = 2.0f * s2 * c2;
            float c4 = fmaf(-2.0f * s2, s2, 1.0f);
            row[0 + d]  = s1;  row[3 + d]  = s2;  row[6 + d]  = s3;  row[9 + d]  = s4;
            row[12 + d] = c1;  row[15 + d] = c2;  row[18 + d] = c3;  row[21 + d] = c4;
        }
    }
#pragma unroll
    for (int c = 0; c < 32; c++) row[24 + c] = 0.0f;

    // Phase 4: second load wave interleaved with consumption.
    uint32_t r2[4][8];
    load4(t2, r2);
    accum4(t0, r0, row + 24);
    uint32_t r3[4][8];
    load4(t3, r3);
    accum4(t1, r1, row + 32);
    accum4(t2, r2, row + 40);
    accum4(t3, r3, row + 48);

    // 7 consecutive 256-bit streaming stores (L2 write-merging friendly).
    float* orow = out + (long long)i * 56;
#pragma unroll
    for (int k = 0; k < 7; k++) stg256cs(orow + 8 * k, row + 8 * k);
}

extern "C" void kernel_launch(void* const* d_in, const int* in_sizes, int n_in,
                              void* d_out, int out_size) {
    const float* x  = (const float*)d_in[0];
    const float* g0 = (const float*)d_in[1];
    const float* g1 = (const float*)d_in[2];
    const float* g2 = (const float*)d_in[3];
    const float* g3 = (const float*)d_in[4];
    float* out = (float*)d_out;

    int n = in_sizes[0] / 3;

    const int TT = 256;
    fused_transpose_kernel<<<(TTOT + TT - 1) / TT, TT>>>(g0, g1, g2, g3);
    mrif_main_kernel<<<(n + 255) / 256, 256>>>(x, out, n);
}